// round 5
// baseline (speedup 1.0000x reference)
#include <cuda_runtime.h>
#include <cuda_bf16.h>
#include <cfloat>

#define NN 20000
#define EE 320000
#define INDIM 256
#define HID 64
#define NH 4
#define CC 64
#define HC 256
#define DFF 128

// ------------------- scratch (no allocations allowed) -------------------
__device__ float g_xh[NN * HC];       // per-layer projected features [n, H*C]
__device__ float g_agg[NN * HC];      // aggregated messages
__device__ float g_as[NN * NH];       // attention src scores
__device__ float g_ad[NN * NH];       // attention dst scores
__device__ int   g_indeg[NN];
__device__ int   g_rowptr[NN + 1];
__device__ int   g_cursor[NN];
__device__ int   g_col[EE + NN];

// ------------------- embed: h = (x @ We + be) * sqrt(HID) -------------------
__global__ void embed_kernel(const float* __restrict__ x,
                             const float* __restrict__ We,
                             const float* __restrict__ be,
                             float* __restrict__ h) {
    __shared__ float xs[4][INDIM];
    int tid = threadIdx.x;            // 256 threads
    int tx = tid & 63;                // out col
    int ty = tid >> 6;                // row within block (0..3)
    int i0 = blockIdx.x * 4;
    #pragma unroll
    for (int rr = 0; rr < 4; rr++) {
        int i = i0 + rr;
        if (i < NN) xs[rr][tid] = x[i * INDIM + tid];
    }
    __syncthreads();
    int i = i0 + ty;
    if (i < NN) {
        float acc = be[tx];
        #pragma unroll 8
        for (int k = 0; k < INDIM; k++)
            acc = fmaf(xs[ty][k], We[k * HID + tx], acc);
        h[i * HID + tx] = acc * 8.0f;   // sqrt(64)
    }
}

// ------------------- CSR build -------------------
__global__ void init_indeg_kernel() {
    int i = blockIdx.x * blockDim.x + threadIdx.x;
    if (i < NN) g_indeg[i] = 1;   // self loop
}

__global__ void hist_kernel(const int* __restrict__ ei) {
    int e = blockIdx.x * blockDim.x + threadIdx.x;
    if (e < EE) atomicAdd(&g_indeg[ei[EE + e]], 1);
}

__global__ void scan_kernel() {
    __shared__ int sm[1024];
    int t = threadIdx.x;
    const int CH = (NN + 1023) / 1024;
    int b0 = t * CH;
    int b1 = b0 + CH; if (b1 > NN) b1 = NN;
    if (b0 > NN) b0 = NN;
    int s = 0;
    for (int i = b0; i < b1; i++) s += g_indeg[i];
    sm[t] = s;
    __syncthreads();
    for (int off = 1; off < 1024; off <<= 1) {
        int v = (t >= off) ? sm[t - off] : 0;
        __syncthreads();
        sm[t] += v;
        __syncthreads();
    }
    int run = sm[t] - s;   // exclusive prefix
    for (int i = b0; i < b1; i++) {
        g_rowptr[i] = run;
        g_cursor[i] = run;
        run += g_indeg[i];
    }
    if (b0 < NN && b1 >= NN) g_rowptr[NN] = run;
}

__global__ void scatter_kernel(const int* __restrict__ ei) {
    int idx = blockIdx.x * blockDim.x + threadIdx.x;
    if (idx >= EE + NN) return;
    int s, d;
    if (idx < EE) { s = ei[idx]; d = ei[EE + idx]; }
    else          { s = d = idx - EE; }
    int p = atomicAdd(&g_cursor[d], 1);
    g_col[p] = s;
}

// ------------------- per-layer: xh = h @ Wc[l]; a_s, a_d reductions -------------------
__global__ void xh_kernel(const float* __restrict__ h,
                          const float* __restrict__ Wc,      // [64,256] for this layer
                          const float* __restrict__ asrc,    // [256]
                          const float* __restrict__ adst) {  // [256]
    __shared__ float hr[HID];
    __shared__ float ssum[8], dsum[8];
    int tid = threadIdx.x;              // 256 threads
    int lane = tid & 31;
    int wid = tid >> 5;
    for (int r = 0; r < 4; r++) {
        int i = blockIdx.x * 4 + r;
        if (i < NN) {
            if (tid < HID) hr[tid] = h[i * HID + tid];
            __syncthreads();
            float acc = 0.0f;
            #pragma unroll 8
            for (int k = 0; k < HID; k++)
                acc = fmaf(hr[k], Wc[k * HC + tid], acc);
            g_xh[i * HC + tid] = acc;
            float vs = acc * asrc[tid];
            float vd = acc * adst[tid];
            #pragma unroll
            for (int off = 16; off > 0; off >>= 1) {
                vs += __shfl_down_sync(0xFFFFFFFFu, vs, off);
                vd += __shfl_down_sync(0xFFFFFFFFu, vd, off);
            }
            if (lane == 0) { ssum[wid] = vs; dsum[wid] = vd; }
            __syncthreads();
            if (tid < NH) {
                g_as[i * NH + tid] = ssum[2 * tid] + ssum[2 * tid + 1];
                g_ad[i * NH + tid] = dsum[2 * tid] + dsum[2 * tid + 1];
            }
            __syncthreads();
        }
    }
}

// ------------------- attention + aggregation: warp per dst node, online softmax -------------------
// Lane L owns columns {2L, 2L+1} of each head's 64-wide slice (float2 loads).
__global__ void attn_kernel(const float* __restrict__ bc) {  // [256] for this layer
    int gwarp = (blockIdx.x * blockDim.x + threadIdx.x) >> 5;
    int lane = threadIdx.x & 31;
    if (gwarp >= NN) return;
    int i = gwarp;
    const float4 adv = *reinterpret_cast<const float4*>(g_ad + i * NH);
    float ad[NH] = {adv.x, adv.y, adv.z, adv.w};
    float m[NH], z[NH];
    float2 acc[NH];
    #pragma unroll
    for (int hh = 0; hh < NH; hh++) {
        m[hh] = -FLT_MAX; z[hh] = 0.0f;
        acc[hh].x = 0.0f; acc[hh].y = 0.0f;
    }

    int beg = g_rowptr[i], end = g_rowptr[i + 1];
    for (int j = beg; j < end; j++) {
        int s = __ldg(&g_col[j]);
        const float* xr = g_xh + s * HC + 2 * lane;
        const float4 asv = __ldg(reinterpret_cast<const float4*>(g_as + s * NH));
        float av[NH] = {asv.x, asv.y, asv.z, asv.w};
        #pragma unroll
        for (int hh = 0; hh < NH; hh++) {
            float e = av[hh] + ad[hh];
            e = (e > 0.0f) ? e : 0.2f * e;
            float mo = m[hh];
            float mn = fmaxf(mo, e);
            float scale = __expf(mo - mn);   // 0 when mo=-FLT_MAX
            float p = __expf(e - mn);
            z[hh] = z[hh] * scale + p;
            float2 xv = __ldg(reinterpret_cast<const float2*>(xr + hh * CC));
            acc[hh].x = fmaf(p, xv.x, acc[hh].x * scale);
            acc[hh].y = fmaf(p, xv.y, acc[hh].y * scale);
            m[hh] = mn;
        }
    }
    #pragma unroll
    for (int hh = 0; hh < NH; hh++) {
        float inv = 1.0f / (z[hh] + 1e-16f);
        int c0 = hh * CC + 2 * lane;
        float2 o;
        o.x = acc[hh].x * inv + bc[c0];
        o.y = acc[hh].y * inv + bc[c0 + 1];
        *reinterpret_cast<float2*>(g_agg + i * HC + c0) = o;
    }
}

// ------------------- FFN + LayerNorm + residual -------------------
__device__ __forceinline__ float gelu_exact(float v) {
    return 0.5f * v * (1.0f + erff(v * 0.7071067811865476f));
}

__global__ void ffn_kernel(const float* __restrict__ W1,   // [256,128]
                           const float* __restrict__ b1,   // [128]
                           const float* __restrict__ W2,   // [128,64]
                           const float* __restrict__ b2,   // [64]
                           const float* __restrict__ lg,   // [64]
                           const float* __restrict__ lb,   // [64]
                           float* __restrict__ h) {
    __shared__ float ts[HC];
    __shared__ float us[DFF];
    __shared__ float fs[HID];
    __shared__ float red[2];
    int tid = threadIdx.x;   // 128 threads
    for (int r = 0; r < 4; r++) {
        int i = blockIdx.x * 4 + r;
        if (i < NN) {
            const float2 t2 = *reinterpret_cast<const float2*>(g_agg + i * HC + tid * 2);
            ts[tid * 2]     = t2.x;
            ts[tid * 2 + 1] = t2.y;
            __syncthreads();
            float u = b1[tid];
            #pragma unroll 8
            for (int k = 0; k < HC; k++)
                u = fmaf(ts[k], W1[k * DFF + tid], u);
            us[tid] = gelu_exact(u);
            __syncthreads();
            if (tid < HID) {
                float f = b2[tid];
                #pragma unroll 8
                for (int d = 0; d < DFF; d++)
                    f = fmaf(us[d], W2[d * HID + tid], f);
                fs[tid] = f;
            }
            __syncthreads();
            if (tid < 32) {
                float sv = fs[tid] + fs[tid + 32];
                #pragma unroll
                for (int off = 16; off > 0; off >>= 1)
                    sv += __shfl_down_sync(0xFFFFFFFFu, sv, off);
                if (tid == 0) red[0] = sv * (1.0f / HID);
            }
            __syncthreads();
            float mean = red[0];
            if (tid < 32) {
                float d0 = fs[tid] - mean, d1 = fs[tid + 32] - mean;
                float sv = d0 * d0 + d1 * d1;
                #pragma unroll
                for (int off = 16; off > 0; off >>= 1)
                    sv += __shfl_down_sync(0xFFFFFFFFu, sv, off);
                if (tid == 0) red[1] = sv * (1.0f / HID);
            }
            __syncthreads();
            float var = red[1];
            if (tid < HID) {
                float y = (fs[tid] - mean) * rsqrtf(var + 1e-5f) * lg[tid] + lb[tid];
                h[i * HID + tid] += y;
            }
            __syncthreads();
        }
    }
}

// ------------------- launch -------------------
extern "C" void kernel_launch(void* const* d_in, const int* in_sizes, int n_in,
                              void* d_out, int out_size) {
    const float* x       = (const float*)d_in[0];
    const int*   ei      = (const int*)  d_in[1];
    const float* We      = (const float*)d_in[2];
    const float* be      = (const float*)d_in[3];
    const float* Wc      = (const float*)d_in[4];
    const float* att_src = (const float*)d_in[5];
    const float* att_dst = (const float*)d_in[6];
    const float* bc      = (const float*)d_in[7];
    const float* W1      = (const float*)d_in[8];
    const float* b1      = (const float*)d_in[9];
    const float* W2      = (const float*)d_in[10];
    const float* b2      = (const float*)d_in[11];
    const float* ln_g    = (const float*)d_in[12];
    const float* ln_b    = (const float*)d_in[13];
    float* h = (float*)d_out;

    // embed
    embed_kernel<<<(NN + 3) / 4, 256>>>(x, We, be, h);

    // CSR build (edges identical across layers -> once per launch)
    init_indeg_kernel<<<(NN + 255) / 256, 256>>>();
    hist_kernel<<<(EE + 255) / 256, 256>>>(ei);
    scan_kernel<<<1, 1024>>>();
    scatter_kernel<<<(EE + NN + 255) / 256, 256>>>(ei);

    for (int l = 0; l < 4; l++) {
        xh_kernel<<<(NN + 3) / 4, 256>>>(h,
                                         Wc + l * HID * HC,
                                         att_src + l * HC,
                                         att_dst + l * HC);
        attn_kernel<<<(NN + 7) / 8, 256>>>(bc + l * HC);
        ffn_kernel<<<(NN + 3) / 4, 128>>>(W1 + l * HC * DFF,
                                          b1 + l * DFF,
                                          W2 + l * DFF * HID,
                                          b2 + l * HID,
                                          ln_g + l * HID,
                                          ln_b + l * HID,
                                          h);
    }
}

// round 7
// speedup vs baseline: 2.0386x; 2.0386x over previous
#include <cuda_runtime.h>
#include <cfloat>

#define NN 20000
#define EE 320000
#define INDIM 256
#define HID 64
#define NH 4
#define CC 64
#define HC 256
#define DFF 128
#define MT 64

typedef unsigned long long u64;

__device__ __forceinline__ u64 pk2(float x, float y) {
    u64 r; asm("mov.b64 %0,{%1,%2};" : "=l"(r) : "f"(x), "f"(y)); return r;
}
__device__ __forceinline__ void upk2(u64 v, float& x, float& y) {
    asm("mov.b64 {%0,%1},%2;" : "=f"(x), "=f"(y) : "l"(v));
}
__device__ __forceinline__ void ffma2(u64& d, u64 a, u64 b) {
    asm("fma.rn.f32x2 %0,%1,%2,%0;" : "+l"(d) : "l"(a), "l"(b));
}
__device__ __forceinline__ u64 ld2g(const float* p) {
    u64 r; asm("ld.global.nc.b64 %0,[%1];" : "=l"(r) : "l"(p)); return r;
}

// ------------------- scratch -------------------
__device__ float g_xh[NN * HC];
__device__ float g_as[NN * NH];
__device__ float g_ad[NN * NH];
__device__ int   g_indeg[NN];
__device__ int   g_rowptr[NN + 1];
__device__ int   g_cursor[NN];
__device__ int   g_col[EE + NN];
__device__ float g_agg[NN * HC];

// ------------------- embed: h = (x @ We + be) * 8 -------------------
// 64-row tile, N=64, K=256 in 4 chunks of 64. Thread (rg,cg): 8 rows x 2 cols.
__global__ __launch_bounds__(256) void embed_kernel(const float* __restrict__ x,
                                                    const float* __restrict__ We,
                                                    const float* __restrict__ be,
                                                    float* __restrict__ h) {
    __shared__ u64 As2[MT][65];
    int tid = threadIdx.x;
    int rg = tid >> 5, cg = tid & 31;
    int row0 = blockIdx.x * MT;
    u64 acc[8];
    #pragma unroll
    for (int r = 0; r < 8; r++) acc[r] = 0ull;

    for (int kc = 0; kc < INDIM; kc += 64) {
        int r = tid >> 2, seg = tid & 3;
        int gr = row0 + r;
        #pragma unroll
        for (int j0 = 0; j0 < 16; j0 += 4) {
            float4 v = (gr < NN) ? *reinterpret_cast<const float4*>(x + gr * INDIM + kc + seg * 16 + j0)
                                 : make_float4(0.f, 0.f, 0.f, 0.f);
            As2[r][seg * 16 + j0 + 0] = pk2(v.x, v.x);
            As2[r][seg * 16 + j0 + 1] = pk2(v.y, v.y);
            As2[r][seg * 16 + j0 + 2] = pk2(v.z, v.z);
            As2[r][seg * 16 + j0 + 3] = pk2(v.w, v.w);
        }
        __syncthreads();
        #pragma unroll 8
        for (int k = 0; k < 64; k++) {
            u64 b2 = ld2g(We + (kc + k) * HID + 2 * cg);
            #pragma unroll
            for (int r2 = 0; r2 < 8; r2++) ffma2(acc[r2], As2[rg * 8 + r2][k], b2);
        }
        __syncthreads();
    }
    float be0 = __ldg(be + 2 * cg), be1 = __ldg(be + 2 * cg + 1);
    #pragma unroll
    for (int r = 0; r < 8; r++) {
        int gr = row0 + rg * 8 + r;
        if (gr < NN) {
            float a0, a1; upk2(acc[r], a0, a1);
            float2 o; o.x = (a0 + be0) * 8.0f; o.y = (a1 + be1) * 8.0f;
            *reinterpret_cast<float2*>(h + gr * HID + 2 * cg) = o;
        }
    }
}

// ------------------- CSR build -------------------
__global__ void init_indeg_kernel() {
    int i = blockIdx.x * blockDim.x + threadIdx.x;
    if (i < NN) g_indeg[i] = 1;
}
__global__ void hist_kernel(const int* __restrict__ ei) {
    int e = blockIdx.x * blockDim.x + threadIdx.x;
    if (e < EE) atomicAdd(&g_indeg[ei[EE + e]], 1);
}
__global__ void scan_kernel() {
    __shared__ int sm[1024];
    int t = threadIdx.x;
    const int CH = (NN + 1023) / 1024;
    int b0 = t * CH;
    int b1 = b0 + CH; if (b1 > NN) b1 = NN;
    if (b0 > NN) b0 = NN;
    int s = 0;
    for (int i = b0; i < b1; i++) s += g_indeg[i];
    sm[t] = s;
    __syncthreads();
    for (int off = 1; off < 1024; off <<= 1) {
        int v = (t >= off) ? sm[t - off] : 0;
        __syncthreads();
        sm[t] += v;
        __syncthreads();
    }
    int run = sm[t] - s;
    for (int i = b0; i < b1; i++) {
        g_rowptr[i] = run;
        g_cursor[i] = run;
        run += g_indeg[i];
    }
    if (b0 < NN && b1 >= NN) g_rowptr[NN] = run;
}
__global__ void scatter_kernel(const int* __restrict__ ei) {
    int idx = blockIdx.x * blockDim.x + threadIdx.x;
    if (idx >= EE + NN) return;
    int s, d;
    if (idx < EE) { s = ei[idx]; d = ei[EE + idx]; }
    else          { s = d = idx - EE; }
    int p = atomicAdd(&g_cursor[d], 1);
    g_col[p] = s;
}

// ------------------- xh = h @ Wc[l]  (M64, N=256, K=64) -------------------
// Thread (rg,cg): 8 rows x 8 cols; cols {2cg+64j} j=0..3 (one colpair per head).
__global__ __launch_bounds__(256) void xh_kernel(const float* __restrict__ h,
                                                 const float* __restrict__ Wc) {
    __shared__ u64 As2[MT][65];
    int tid = threadIdx.x;
    int rg = tid >> 5, cg = tid & 31;
    int row0 = blockIdx.x * MT;
    u64 acc[8][4];
    #pragma unroll
    for (int r = 0; r < 8; r++)
        #pragma unroll
        for (int j = 0; j < 4; j++) acc[r][j] = 0ull;

    {
        int r = tid >> 2, seg = tid & 3;
        int gr = row0 + r;
        #pragma unroll
        for (int j0 = 0; j0 < 16; j0 += 4) {
            float4 v = (gr < NN) ? *reinterpret_cast<const float4*>(h + gr * HID + seg * 16 + j0)
                                 : make_float4(0.f, 0.f, 0.f, 0.f);
            As2[r][seg * 16 + j0 + 0] = pk2(v.x, v.x);
            As2[r][seg * 16 + j0 + 1] = pk2(v.y, v.y);
            As2[r][seg * 16 + j0 + 2] = pk2(v.z, v.z);
            As2[r][seg * 16 + j0 + 3] = pk2(v.w, v.w);
        }
    }
    __syncthreads();
    #pragma unroll 4
    for (int k = 0; k < HID; k++) {
        u64 b[4];
        #pragma unroll
        for (int j = 0; j < 4; j++) b[j] = ld2g(Wc + k * HC + 2 * cg + 64 * j);
        #pragma unroll
        for (int r = 0; r < 8; r++) {
            u64 a2 = As2[rg * 8 + r][k];
            #pragma unroll
            for (int j = 0; j < 4; j++) ffma2(acc[r][j], a2, b[j]);
        }
    }
    #pragma unroll
    for (int r = 0; r < 8; r++) {
        int gr = row0 + rg * 8 + r;
        if (gr < NN) {
            #pragma unroll
            for (int j = 0; j < 4; j++) {
                float a0, a1; upk2(acc[r][j], a0, a1);
                float2 o; o.x = a0; o.y = a1;
                *reinterpret_cast<float2*>(g_xh + gr * HC + 2 * cg + 64 * j) = o;
            }
        }
    }
}

// ------------------- attention scores a_s, a_d (warp per node) -------------------
__global__ void score_kernel(const float* __restrict__ asrc,
                             const float* __restrict__ adst) {
    int node = blockIdx.x * 8 + (threadIdx.x >> 5);
    int lane = threadIdx.x & 31;
    if (node >= NN) return;
    const float* xr = g_xh + node * HC;
    float4 xa = *reinterpret_cast<const float4*>(xr + 4 * lane);
    float4 xb = *reinterpret_cast<const float4*>(xr + 128 + 4 * lane);
    float4 sa = __ldg(reinterpret_cast<const float4*>(asrc + 4 * lane));
    float4 sb = __ldg(reinterpret_cast<const float4*>(asrc + 128 + 4 * lane));
    float4 da = __ldg(reinterpret_cast<const float4*>(adst + 4 * lane));
    float4 db = __ldg(reinterpret_cast<const float4*>(adst + 128 + 4 * lane));
    float psA = xa.x * sa.x + xa.y * sa.y + xa.z * sa.z + xa.w * sa.w;
    float psB = xb.x * sb.x + xb.y * sb.y + xb.z * sb.z + xb.w * sb.w;
    float pdA = xa.x * da.x + xa.y * da.y + xa.z * da.z + xa.w * da.w;
    float pdB = xb.x * db.x + xb.y * db.y + xb.z * db.z + xb.w * db.w;
    #pragma unroll
    for (int off = 8; off > 0; off >>= 1) {
        psA += __shfl_xor_sync(0xFFFFFFFFu, psA, off);
        psB += __shfl_xor_sync(0xFFFFFFFFu, psB, off);
        pdA += __shfl_xor_sync(0xFFFFFFFFu, pdA, off);
        pdB += __shfl_xor_sync(0xFFFFFFFFu, pdB, off);
    }
    if ((lane & 15) == 0) {
        int hh = lane >> 4;   // 0 or 1
        g_as[node * NH + hh]     = psA;
        g_as[node * NH + 2 + hh] = psB;
        g_ad[node * NH + hh]     = pdA;
        g_ad[node * NH + 2 + hh] = pdB;
    }
}

// ------------------- attention aggregation: warp per dst, two-pass softmax -------------------
__global__ void attn_kernel(const float* __restrict__ bc) {
    int i = (blockIdx.x * blockDim.x + threadIdx.x) >> 5;
    int lane = threadIdx.x & 31;
    if (i >= NN) return;
    const float4 adv = *reinterpret_cast<const float4*>(g_ad + i * NH);
    float ad[NH] = {adv.x, adv.y, adv.z, adv.w};
    int beg = g_rowptr[i], end = g_rowptr[i + 1];

    // pass 1: max
    float m[NH];
    #pragma unroll
    for (int hh = 0; hh < NH; hh++) m[hh] = -FLT_MAX;
    for (int j = beg; j < end; j++) {
        int s = __ldg(&g_col[j]);
        const float4 asv = __ldg(reinterpret_cast<const float4*>(g_as + s * NH));
        float av[NH] = {asv.x, asv.y, asv.z, asv.w};
        #pragma unroll
        for (int hh = 0; hh < NH; hh++) {
            float e = av[hh] + ad[hh];
            e = (e > 0.0f) ? e : 0.2f * e;
            m[hh] = fmaxf(m[hh], e);
        }
    }
    // pass 2: exp-weighted accumulation
    float z[NH];
    float2 acc[NH];
    #pragma unroll
    for (int hh = 0; hh < NH; hh++) { z[hh] = 0.0f; acc[hh].x = 0.0f; acc[hh].y = 0.0f; }
    for (int j = beg; j < end; j++) {
        int s = __ldg(&g_col[j]);
        const float4 asv = __ldg(reinterpret_cast<const float4*>(g_as + s * NH));
        float av[NH] = {asv.x, asv.y, asv.z, asv.w};
        const float* xr = g_xh + s * HC + 2 * lane;
        #pragma unroll
        for (int hh = 0; hh < NH; hh++) {
            float e = av[hh] + ad[hh];
            e = (e > 0.0f) ? e : 0.2f * e;
            float p = __expf(e - m[hh]);
            z[hh] += p;
            float2 xv = __ldg(reinterpret_cast<const float2*>(xr + hh * CC));
            acc[hh].x = fmaf(p, xv.x, acc[hh].x);
            acc[hh].y = fmaf(p, xv.y, acc[hh].y);
        }
    }
    #pragma unroll
    for (int hh = 0; hh < NH; hh++) {
        float inv = 1.0f / (z[hh] + 1e-16f);
        int c0 = hh * CC + 2 * lane;
        float2 o;
        o.x = acc[hh].x * inv + __ldg(bc + c0);
        o.y = acc[hh].y * inv + __ldg(bc + c0 + 1);
        *reinterpret_cast<float2*>(g_agg + i * HC + c0) = o;
    }
}

// ------------------- FFN + LayerNorm + residual (fused, 64-row tile) -------------------
__device__ __forceinline__ float gelu_exact(float v) {
    return 0.5f * v * (1.0f + erff(v * 0.7071067811865476f));
}

__global__ __launch_bounds__(256) void ffn_kernel(const float* __restrict__ W1,
                                                  const float* __restrict__ b1,
                                                  const float* __restrict__ W2,
                                                  const float* __restrict__ b2,
                                                  const float* __restrict__ lg,
                                                  const float* __restrict__ lb,
                                                  float* __restrict__ h) {
    __shared__ u64 As2[MT][17];
    __shared__ float Us[MT][DFF];
    int tid = threadIdx.x;
    int rg = tid >> 5, cg = tid & 31;
    int row0 = blockIdx.x * MT;

    // ---- stage 1: U = gelu(T @ W1 + b1), T = g_agg rows ----
    u64 acc[8][2];
    #pragma unroll
    for (int r = 0; r < 8; r++) { acc[r][0] = 0ull; acc[r][1] = 0ull; }

    for (int kc = 0; kc < HC; kc += 16) {
        int r = tid >> 2, seg = tid & 3;
        int gr = row0 + r;
        float4 v = (gr < NN) ? *reinterpret_cast<const float4*>(g_agg + gr * HC + kc + seg * 4)
                             : make_float4(0.f, 0.f, 0.f, 0.f);
        As2[r][seg * 4 + 0] = pk2(v.x, v.x);
        As2[r][seg * 4 + 1] = pk2(v.y, v.y);
        As2[r][seg * 4 + 2] = pk2(v.z, v.z);
        As2[r][seg * 4 + 3] = pk2(v.w, v.w);
        __syncthreads();
        #pragma unroll
        for (int k = 0; k < 16; k++) {
            u64 b0 = ld2g(W1 + (kc + k) * DFF + 2 * cg);
            u64 bb1 = ld2g(W1 + (kc + k) * DFF + 2 * cg + 64);
            #pragma unroll
            for (int r2 = 0; r2 < 8; r2++) {
                u64 a2 = As2[rg * 8 + r2][k];
                ffma2(acc[r2][0], a2, b0);
                ffma2(acc[r2][1], a2, bb1);
            }
        }
        __syncthreads();
    }
    {
        float bi00 = __ldg(b1 + 2 * cg), bi01 = __ldg(b1 + 2 * cg + 1);
        float bi10 = __ldg(b1 + 2 * cg + 64), bi11 = __ldg(b1 + 2 * cg + 65);
        #pragma unroll
        for (int r = 0; r < 8; r++) {
            float a0, a1; upk2(acc[r][0], a0, a1);
            Us[rg * 8 + r][2 * cg]      = gelu_exact(a0 + bi00);
            Us[rg * 8 + r][2 * cg + 1]  = gelu_exact(a1 + bi01);
            upk2(acc[r][1], a0, a1);
            Us[rg * 8 + r][2 * cg + 64] = gelu_exact(a0 + bi10);
            Us[rg * 8 + r][2 * cg + 65] = gelu_exact(a1 + bi11);
        }
    }
    __syncthreads();

    // ---- stage 2: F = U @ W2 + b2 ----
    u64 acc2[8];
    #pragma unroll
    for (int r = 0; r < 8; r++) acc2[r] = 0ull;
    #pragma unroll 4
    for (int k = 0; k < DFF; k++) {
        u64 b2v = ld2g(W2 + k * HID + 2 * cg);
        #pragma unroll
        for (int r = 0; r < 8; r++) {
            float a = Us[rg * 8 + r][k];
            ffma2(acc2[r], pk2(a, a), b2v);
        }
    }
    __syncthreads();   // done reading Us; reuse its storage for F (stride 65)

    float* Fs = &Us[0][0];
    {
        float c0 = __ldg(b2 + 2 * cg), c1 = __ldg(b2 + 2 * cg + 1);
        #pragma unroll
        for (int r = 0; r < 8; r++) {
            float a0, a1; upk2(acc2[r], a0, a1);
            Fs[(rg * 8 + r) * 65 + 2 * cg]     = a0 + c0;
            Fs[(rg * 8 + r) * 65 + 2 * cg + 1] = a1 + c1;
        }
    }
    __syncthreads();

    // ---- LayerNorm + residual: 4 threads per row ----
    {
        int row = tid >> 2, t4 = tid & 3;
        int gr = row0 + row;
        float s = 0.0f, ss = 0.0f;
        #pragma unroll
        for (int c = 0; c < 16; c++) {
            float f = Fs[row * 65 + t4 * 16 + c];
            s += f; ss += f * f;
        }
        s  += __shfl_xor_sync(0xFFFFFFFFu, s, 1);
        s  += __shfl_xor_sync(0xFFFFFFFFu, s, 2);
        ss += __shfl_xor_sync(0xFFFFFFFFu, ss, 1);
        ss += __shfl_xor_sync(0xFFFFFFFFu, ss, 2);
        float mean = s * (1.0f / HID);
        float var = fmaxf(ss * (1.0f / HID) - mean * mean, 0.0f);
        float rstd = rsqrtf(var + 1e-5f);
        if (gr < NN) {
            #pragma unroll
            for (int c = 0; c < 16; c++) {
                int col = t4 * 16 + c;
                float y = (Fs[row * 65 + col] - mean) * rstd * __ldg(lg + col) + __ldg(lb + col);
                h[gr * HID + col] += y;
            }
        }
    }
}

// ------------------- launch -------------------
extern "C" void kernel_launch(void* const* d_in, const int* in_sizes, int n_in,
                              void* d_out, int out_size) {
    const float* x       = (const float*)d_in[0];
    const int*   ei      = (const int*)  d_in[1];
    const float* We      = (const float*)d_in[2];
    const float* be      = (const float*)d_in[3];
    const float* Wc      = (const float*)d_in[4];
    const float* att_src = (const float*)d_in[5];
    const float* att_dst = (const float*)d_in[6];
    const float* bc      = (const float*)d_in[7];
    const float* W1      = (const float*)d_in[8];
    const float* b1      = (const float*)d_in[9];
    const float* W2      = (const float*)d_in[10];
    const float* b2      = (const float*)d_in[11];
    const float* ln_g    = (const float*)d_in[12];
    const float* ln_b    = (const float*)d_in[13];
    float* h = (float*)d_out;

    const int MB = (NN + MT - 1) / MT;   // 313

    embed_kernel<<<MB, 256>>>(x, We, be, h);

    init_indeg_kernel<<<(NN + 255) / 256, 256>>>();
    hist_kernel<<<(EE + 255) / 256, 256>>>(ei);
    scan_kernel<<<1, 1024>>>();
    scatter_kernel<<<(EE + NN + 255) / 256, 256>>>(ei);

    for (int l = 0; l < 4; l++) {
        xh_kernel<<<MB, 256>>>(h, Wc + l * HID * HC);
        score_kernel<<<NN / 8, 256>>>(att_src + l * HC, att_dst + l * HC);
        attn_kernel<<<NN / 8, 256>>>(bc + l * HC);
        ffn_kernel<<<MB, 256>>>(W1 + l * HC * DFF, b1 + l * DFF,
                                W2 + l * DFF * HID, b2 + l * HID,
                                ln_g + l * HID, ln_b + l * HID, h);
    }
}